// round 1
// baseline (speedup 1.0000x reference)
#include <cuda_runtime.h>
#include <math.h>

// Problem dims
#define S_TOT 4096     // BS*N
#define D_DIM 1024
#define T_DIM 2048
#define V_DIM 32000
#define NB 8
#define NC 4
#define DCv 64
#define NH 256

// Scratch (device globals — allocation-free rule)
__device__ float g_x[S_TOT * D_DIM];        // 16 MB: embed out / fan_in out
__device__ float g_xb[S_TOT * T_DIM];       // 32 MB: x_blocks
__device__ float g_zhat[S_TOT * NB * DCv];  // 8 MB:  z_hat_prev
__device__ float g_pcm[2 * S_TOT * NB];     // per-block pcm partials (r=1,2)

// ---------------------------------------------------------------------------
// Embedding gather + pos add
// ---------------------------------------------------------------------------
__global__ void embed_kernel(const int* __restrict__ ids,
                             const float* __restrict__ emb,
                             const float* __restrict__ pos,
                             float* __restrict__ x) {
    int s = blockIdx.x;        // 0..4095
    int q = threadIdx.x;       // 0..255 float4 lanes
    int id = ids[s];
    float4 e = ((const float4*)(emb + (size_t)id * D_DIM))[q];
    float4 p = ((const float4*)(pos + (size_t)(s & 1023) * D_DIM))[q];
    float4 o;
    o.x = e.x + p.x; o.y = e.y + p.y; o.z = e.z + p.z; o.w = e.w + p.w;
    ((float4*)(x + (size_t)s * D_DIM))[q] = o;
}

// ---------------------------------------------------------------------------
// Generic fp32 GEMM: C[M,N] = A[M,K] @ B (+bias)
// TB=0: B is [K,N] row-major.  TB=1: B is [N,K] row-major (NT / B^T).
// 128x128 block tile, Ktile=8, 256 threads, 8x8 per-thread microtile.
// All dims assumed multiples of 128 (M) / 128 (N) / 8 (K) — true here.
// ---------------------------------------------------------------------------
template <int TB>
__global__ __launch_bounds__(256) void gemm_f32(
    const float* __restrict__ A, const float* __restrict__ Bm,
    const float* __restrict__ bias, float* __restrict__ C,
    int M, int N, int K) {
    __shared__ float As[8][128];
    __shared__ float Bs[8][128];
    const int tid = threadIdx.x;
    const int bm = blockIdx.x * 128;   // M tile fastest -> B reuse in L2
    const int bn = blockIdx.y * 128;
    const int tx = tid & 15, ty = tid >> 4;
    const int mt = ty * 8, nt = tx * 8;
    float acc[8][8] = {};
    const int ar = tid >> 1, ak = (tid & 1) * 4;
    int bk, bn2;
    if (TB == 0) { bk = tid >> 5; bn2 = (tid & 31) * 4; }
    else         { bk = (tid & 1) * 4; bn2 = tid >> 1; }

    for (int k0 = 0; k0 < K; k0 += 8) {
        float4 av = *(const float4*)(A + (size_t)(bm + ar) * K + k0 + ak);
        As[ak + 0][ar] = av.x; As[ak + 1][ar] = av.y;
        As[ak + 2][ar] = av.z; As[ak + 3][ar] = av.w;
        if (TB == 0) {
            float4 bv = *(const float4*)(Bm + (size_t)(k0 + bk) * N + bn + bn2);
            *(float4*)&Bs[bk][bn2] = bv;
        } else {
            float4 bv = *(const float4*)(Bm + (size_t)(bn + bn2) * K + k0 + bk);
            Bs[bk + 0][bn2] = bv.x; Bs[bk + 1][bn2] = bv.y;
            Bs[bk + 2][bn2] = bv.z; Bs[bk + 3][bn2] = bv.w;
        }
        __syncthreads();
#pragma unroll
        for (int kk = 0; kk < 8; kk++) {
            float ra[8], rb[8];
            *(float4*)&ra[0] = *(const float4*)&As[kk][mt];
            *(float4*)&ra[4] = *(const float4*)&As[kk][mt + 4];
            *(float4*)&rb[0] = *(const float4*)&Bs[kk][nt];
            *(float4*)&rb[4] = *(const float4*)&Bs[kk][nt + 4];
#pragma unroll
            for (int i = 0; i < 8; i++)
#pragma unroll
                for (int j = 0; j < 8; j++)
                    acc[i][j] = fmaf(ra[i], rb[j], acc[i][j]);
        }
        __syncthreads();
    }
    float bv[8];
#pragma unroll
    for (int j = 0; j < 8; j++) bv[j] = bias ? bias[bn + nt + j] : 0.0f;
#pragma unroll
    for (int i = 0; i < 8; i++) {
        float* crow = C + (size_t)(bm + mt + i) * N + bn + nt;
        float4 v0, v1;
        v0.x = acc[i][0] + bv[0]; v0.y = acc[i][1] + bv[1];
        v0.z = acc[i][2] + bv[2]; v0.w = acc[i][3] + bv[3];
        v1.x = acc[i][4] + bv[4]; v1.y = acc[i][5] + bv[5];
        v1.z = acc[i][6] + bv[6]; v1.w = acc[i][7] + bv[7];
        *(float4*)crow = v0;
        *(float4*)(crow + 4) = v1;
    }
}

// ---------------------------------------------------------------------------
// Z pass (before MLP update of pass r):
//   z = mean_c xb ; if r>0 accumulate (zhat_prev - z)^2 partials ; zhat_prev = z@Wz[t]
// One block of 64 threads per (s, t).
// ---------------------------------------------------------------------------
__global__ void zpass_kernel(const float* __restrict__ xb,
                             const float* __restrict__ Wz,
                             float* __restrict__ zhat,
                             float* __restrict__ pcm, int r) {
    __shared__ float zs[64];
    __shared__ float red[64];
    const int st = blockIdx.x;   // s*8 + t
    const int t = st & 7;
    const int d = threadIdx.x;
    const float* xp = xb + (size_t)st * 256;  // (s*8+t)*4*64
    float z = 0.25f * (xp[d] + xp[64 + d] + xp[128 + d] + xp[192 + d]);
    zs[d] = z;
    float sq = 0.0f;
    if (r > 0) {
        float diff = zhat[(size_t)st * 64 + d] - z;
        sq = diff * diff;
    }
    __syncthreads();
    const float* wz = Wz + t * 4096;
    float acc = 0.0f;
#pragma unroll
    for (int k = 0; k < 64; k++) acc = fmaf(zs[k], wz[k * 64 + d], acc);
    red[d] = sq;
    __syncthreads();
    for (int o = 32; o > 0; o >>= 1) {
        if (d < o) red[d] += red[d + o];
        __syncthreads();
    }
    if (r > 0 && d == 0) pcm[(size_t)(r - 1) * (S_TOT * NB) + st] = red[0];
    zhat[(size_t)st * 64 + d] = acc;
}

// ---------------------------------------------------------------------------
// Fused refine MLP: per block-column t, per 64-row tile:
//   H = gelu(X[64x64] @ W1[t][64x256]) ; xb += scale * (H @ W2[t][256x64])
// scale = 1 (r==0) else sigmoid(lambda_logit).
// SMEM: Xs[64][68] + W1s[64][256] + W2s[256][64] + Hs[256][65] = 215040 B
// ---------------------------------------------------------------------------
__global__ __launch_bounds__(256) void mlp_kernel(
    float* __restrict__ xb, const float* __restrict__ W1,
    const float* __restrict__ W2, const float* __restrict__ lam_logit, int r) {
    extern __shared__ float sm[];
    float* Xs  = sm;                  // [64][68] k-major (d, row)
    float* W1s = Xs + 64 * 68;        // [64][256]
    float* W2s = W1s + 64 * 256;      // [256][64]
    float* Hs  = W2s + 256 * 64;      // [256][65] (h, row)
    const int tid = threadIdx.x;
    const int t = blockIdx.y;
    const int rt = blockIdx.x;        // 0..255 (16384 rows / 64)
    float lam = 1.0f;
    if (r > 0) lam = 1.0f / (1.0f + expf(-lam_logit[0]));

    // Load X tile (transposed into k-major). Row g -> (s,c); xb[(s*32+t*4+c)*64 + :]
#pragma unroll
    for (int it = 0; it < 4; it++) {
        int idx = tid + 256 * it;       // float4 index in 64x64 tile
        int lr = idx >> 4;
        int q  = idx & 15;
        int g = rt * 64 + lr;
        int s = g >> 2, c = g & 3;
        float4 v = *(const float4*)(xb + (size_t)(s * 32 + t * 4 + c) * 64 + q * 4);
        Xs[(q * 4 + 0) * 68 + lr] = v.x;
        Xs[(q * 4 + 1) * 68 + lr] = v.y;
        Xs[(q * 4 + 2) * 68 + lr] = v.z;
        Xs[(q * 4 + 3) * 68 + lr] = v.w;
    }
    const float4* w1g = (const float4*)(W1 + (size_t)t * 64 * 256);
    const float4* w2g = (const float4*)(W2 + (size_t)t * 256 * 64);
    float4* w1s4 = (float4*)W1s;
    float4* w2s4 = (float4*)W2s;
#pragma unroll
    for (int it = 0; it < 16; it++) {
        w1s4[tid + 256 * it] = w1g[tid + 256 * it];
        w2s4[tid + 256 * it] = w2g[tid + 256 * it];
    }
    __syncthreads();

    // Step 1: H[64x256] = gelu(X @ W1), 8x8 microtile per thread
    {
        const int tx = tid & 31, ty = tid >> 5;
        const int n0 = tx * 8, m0 = ty * 8;
        float acc[8][8] = {};
        for (int k = 0; k < 64; k++) {
            float ra[8], rb[8];
            *(float4*)&ra[0] = *(const float4*)&Xs[k * 68 + m0];
            *(float4*)&ra[4] = *(const float4*)&Xs[k * 68 + m0 + 4];
            *(float4*)&rb[0] = *(const float4*)&W1s[k * 256 + n0];
            *(float4*)&rb[4] = *(const float4*)&W1s[k * 256 + n0 + 4];
#pragma unroll
            for (int i = 0; i < 8; i++)
#pragma unroll
                for (int j = 0; j < 8; j++)
                    acc[i][j] = fmaf(ra[i], rb[j], acc[i][j]);
        }
#pragma unroll
        for (int j = 0; j < 8; j++)
#pragma unroll
            for (int i = 0; i < 8; i++) {
                float v = acc[i][j];
                float u = 0.7978845608028654f * (v + 0.044715f * v * v * v);
                Hs[(n0 + j) * 65 + m0 + i] = 0.5f * v * (1.0f + tanhf(u));
            }
    }
    __syncthreads();

    // Step 2: Delta[64x64] = H @ W2 ; xb += lam * Delta. 4x4 microtile.
    {
        const int tx = tid & 15, ty = tid >> 4;
        const int n0 = tx * 4, m0 = ty * 4;
        float acc[4][4] = {};
        for (int k = 0; k < 256; k++) {
            float ra[4], rb[4];
            ra[0] = Hs[k * 65 + m0 + 0];
            ra[1] = Hs[k * 65 + m0 + 1];
            ra[2] = Hs[k * 65 + m0 + 2];
            ra[3] = Hs[k * 65 + m0 + 3];
            *(float4*)&rb[0] = *(const float4*)&W2s[k * 64 + n0];
#pragma unroll
            for (int i = 0; i < 4; i++)
#pragma unroll
                for (int j = 0; j < 4; j++)
                    acc[i][j] = fmaf(ra[i], rb[j], acc[i][j]);
        }
#pragma unroll
        for (int i = 0; i < 4; i++) {
            int g = rt * 64 + m0 + i;
            int s = g >> 2, c = g & 3;
            float* p = xb + (size_t)(s * 32 + t * 4 + c) * 64 + n0;
            float4 old = *(const float4*)p;
            old.x += lam * acc[i][0];
            old.y += lam * acc[i][1];
            old.z += lam * acc[i][2];
            old.w += lam * acc[i][3];
            *(float4*)p = old;
        }
    }
}

// ---------------------------------------------------------------------------
// LayerNorm (in place), one block per row of 1024
// ---------------------------------------------------------------------------
__global__ void ln_kernel(float* __restrict__ x, const float* __restrict__ g,
                          const float* __restrict__ b) {
    __shared__ float red[256];
    const int s = blockIdx.x, tid = threadIdx.x;
    float4* row = (float4*)(x + (size_t)s * D_DIM);
    float4 v = row[tid];
    red[tid] = v.x + v.y + v.z + v.w;
    __syncthreads();
    for (int o = 128; o > 0; o >>= 1) {
        if (tid < o) red[tid] += red[tid + o];
        __syncthreads();
    }
    float mu = red[0] * (1.0f / 1024.0f);
    __syncthreads();
    float dx = v.x - mu, dy = v.y - mu, dz = v.z - mu, dw = v.w - mu;
    red[tid] = dx * dx + dy * dy + dz * dz + dw * dw;
    __syncthreads();
    for (int o = 128; o > 0; o >>= 1) {
        if (tid < o) red[tid] += red[tid + o];
        __syncthreads();
    }
    float rstd = rsqrtf(red[0] * (1.0f / 1024.0f) + 1e-5f);
    float4 gg = ((const float4*)g)[tid];
    float4 bb = ((const float4*)b)[tid];
    float4 o4;
    o4.x = dx * rstd * gg.x + bb.x;
    o4.y = dy * rstd * gg.y + bb.y;
    o4.z = dz * rstd * gg.z + bb.z;
    o4.w = dw * rstd * gg.w + bb.w;
    row[tid] = o4;
}

// ---------------------------------------------------------------------------
// Deterministic aux reduction: aux = 0.1 * sum(pcm partials) / (S*Dc)
// ---------------------------------------------------------------------------
__global__ void aux_kernel(const float* __restrict__ pcm, float* __restrict__ out) {
    __shared__ float red[256];
    const int tid = threadIdx.x;
    float s = 0.0f;
    for (int i = tid; i < 2 * S_TOT * NB; i += 256) s += pcm[i];
    red[tid] = s;
    __syncthreads();
    for (int o = 128; o > 0; o >>= 1) {
        if (tid < o) red[tid] += red[tid + o];
        __syncthreads();
    }
    if (tid == 0) out[0] = 0.1f * red[0] / 262144.0f;  // /(4096*64)
}

// ---------------------------------------------------------------------------
extern "C" void kernel_launch(void* const* d_in, const int* in_sizes, int n_in,
                              void* d_out, int out_size) {
    const int*   ids  = (const int*)d_in[0];
    const float* emb  = (const float*)d_in[1];
    const float* pos  = (const float*)d_in[2];
    const float* fo_w = (const float*)d_in[3];
    const float* fo_b = (const float*)d_in[4];
    const float* W1   = (const float*)d_in[5];
    const float* W2   = (const float*)d_in[6];
    const float* Wz   = (const float*)d_in[7];
    const float* fi_w = (const float*)d_in[8];
    const float* fi_b = (const float*)d_in[9];
    const float* ln_g = (const float*)d_in[10];
    const float* ln_b = (const float*)d_in[11];
    const float* lamp = (const float*)d_in[12];
    float* out = (float*)d_out;

    float *x, *xb, *zhat, *pcm;
    cudaGetSymbolAddress((void**)&x,    g_x);
    cudaGetSymbolAddress((void**)&xb,   g_xb);
    cudaGetSymbolAddress((void**)&zhat, g_zhat);
    cudaGetSymbolAddress((void**)&pcm,  g_pcm);

    const int MLP_SMEM = (64 * 68 + 64 * 256 + 256 * 64 + 256 * 65) * 4; // 215040
    cudaFuncSetAttribute(mlp_kernel, cudaFuncAttributeMaxDynamicSharedMemorySize,
                         MLP_SMEM);

    // 1. embed
    embed_kernel<<<S_TOT, 256>>>(ids, emb, pos, x);

    // 2. fan_out: xb = x @ fo_w + fo_b   [4096,2048]
    gemm_f32<0><<<dim3(S_TOT / 128, T_DIM / 128), 256>>>(x, fo_w, fo_b, xb,
                                                         S_TOT, T_DIM, D_DIM);

    // 3. refine passes
    for (int r = 0; r < 3; r++) {
        zpass_kernel<<<S_TOT * NB, 64>>>(xb, Wz, zhat, pcm, r);
        mlp_kernel<<<dim3(256, NB), 256, MLP_SMEM>>>(xb, W1, W2, lamp, r);
    }

    // 4. fan_in: x = xb @ fi_w + fi_b   [4096,1024]
    gemm_f32<0><<<dim3(S_TOT / 128, D_DIM / 128), 256>>>(xb, fi_w, fi_b, x,
                                                         S_TOT, D_DIM, T_DIM);

    // 5. layernorm (in place)
    ln_kernel<<<S_TOT, 256>>>(x, ln_g, ln_b);

    // 6. logits = x @ embedding^T -> d_out   [4096,32000]
    gemm_f32<1><<<dim3(S_TOT / 128, V_DIM / 128), 256>>>(x, emb, (const float*)0,
                                                         out, S_TOT, V_DIM, D_DIM);

    // 7. aux loss appended after logits
    if (out_size > S_TOT * V_DIM) {
        aux_kernel<<<1, 256>>>(pcm, out + (size_t)S_TOT * V_DIM);
    }
}

// round 4
// speedup vs baseline: 2.6037x; 2.6037x over previous
#include <cuda_runtime.h>
#include <cuda_fp16.h>
#include <stdint.h>
#include <math.h>

// Problem dims
#define S_TOT 4096     // BS*N
#define D_DIM 1024
#define T_DIM 2048
#define V_DIM 32000
#define NB 8

// Scratch (device globals — allocation-free rule)
__device__ float g_x[S_TOT * D_DIM];        // 16 MB
__device__ float g_xb[S_TOT * T_DIM];       // 32 MB
__device__ float g_zhat[S_TOT * NB * 64];   // 8 MB
__device__ float g_pcm[2 * S_TOT * NB];
__device__ __half g_Ah[(size_t)S_TOT * 2048];   // 16 MB: [ah | al] split fp16
__device__ __half g_Bh[(size_t)V_DIM * 1024];   // 65 MB: emb fp16

__device__ __forceinline__ uint32_t smem_u32(const void* p) {
    uint32_t a;
    asm("{ .reg .u64 t; cvta.to.shared.u64 t, %1; cvt.u32.u64 %0, t; }"
        : "=r"(a) : "l"(p));
    return a;
}

// ---------------------------------------------------------------------------
// fp16 split conversions
// ---------------------------------------------------------------------------
__global__ void convA_h(const float* __restrict__ x, __half* __restrict__ Ah) {
    int row = blockIdx.x;
    int q = threadIdx.x;  // 0..255, 4 elems
    float4 v = ((const float4*)(x + (size_t)row * 1024))[q];
    __half h0 = __float2half_rn(v.x), h1 = __float2half_rn(v.y);
    __half h2 = __float2half_rn(v.z), h3 = __float2half_rn(v.w);
    __half l0 = __float2half_rn(v.x - __half2float(h0));
    __half l1 = __float2half_rn(v.y - __half2float(h1));
    __half l2 = __float2half_rn(v.z - __half2float(h2));
    __half l3 = __float2half_rn(v.w - __half2float(h3));
    uint2 H, L;
    H.x = (uint32_t)__half_as_ushort(h0) | ((uint32_t)__half_as_ushort(h1) << 16);
    H.y = (uint32_t)__half_as_ushort(h2) | ((uint32_t)__half_as_ushort(h3) << 16);
    L.x = (uint32_t)__half_as_ushort(l0) | ((uint32_t)__half_as_ushort(l1) << 16);
    L.y = (uint32_t)__half_as_ushort(l2) | ((uint32_t)__half_as_ushort(l3) << 16);
    __half* base = Ah + (size_t)row * 2048 + q * 4;
    *(uint2*)base = H;
    *(uint2*)(base + 1024) = L;
}

__global__ void convB_h(const float* __restrict__ emb, __half* __restrict__ Bh) {
    size_t i = (size_t)blockIdx.x * 256 + threadIdx.x;  // float4 index
    float4 v = ((const float4*)emb)[i];
    uint2 H;
    H.x = (uint32_t)__half_as_ushort(__float2half_rn(v.x)) |
          ((uint32_t)__half_as_ushort(__float2half_rn(v.y)) << 16);
    H.y = (uint32_t)__half_as_ushort(__float2half_rn(v.z)) |
          ((uint32_t)__half_as_ushort(__float2half_rn(v.w)) << 16);
    ((uint2*)Bh)[i] = H;
}

// ---------------------------------------------------------------------------
// HMMA fp16 GEMM: C[4096,32000] = Ah[4096,2048] @ Bh[32000,1024]^T
// (B k-index wraps at 1024: both A halves multiply the same B.)
// CTA tile 128x128, 8 warps (warp tile 64x32), cp.async double buffer, k=64.
// ---------------------------------------------------------------------------
#define HBUF 32768
#define HSMEM (2 * HBUF)

__device__ __forceinline__ void ldsm4(uint32_t* r, uint32_t addr) {
    asm volatile("ldmatrix.sync.aligned.m8n8.x4.shared.b16 {%0,%1,%2,%3}, [%4];"
                 : "=r"(r[0]), "=r"(r[1]), "=r"(r[2]), "=r"(r[3]) : "r"(addr));
}
__device__ __forceinline__ void mma16816(float* c, const uint32_t* a,
                                         uint32_t b0, uint32_t b1) {
    asm volatile(
        "mma.sync.aligned.m16n8k16.row.col.f32.f16.f16.f32 "
        "{%0,%1,%2,%3}, {%4,%5,%6,%7}, {%8,%9}, {%0,%1,%2,%3};"
        : "+f"(c[0]), "+f"(c[1]), "+f"(c[2]), "+f"(c[3])
        : "r"(a[0]), "r"(a[1]), "r"(a[2]), "r"(a[3]), "r"(b0), "r"(b1));
}

__global__ __launch_bounds__(256) void gemm_hmma(
    const __half* __restrict__ Ah, const __half* __restrict__ Bh,
    float* __restrict__ C) {
    extern __shared__ __align__(128) char smem[];
    const uint32_t sb = smem_u32(smem);
    const int tid = threadIdx.x, lane = tid & 31, wid = tid >> 5;
    const int bm = blockIdx.x * 128, bn = blockIdx.y * 128;
    const int wm = (wid & 1) * 64, wn = (wid >> 1) * 32;

    float acc[4][4][4] = {};

    // per-thread cp.async source/dest (4 x 16B each for A and B per chunk)
    auto issue = [&](int ch, int buf) {
        int k0 = ch * 64;
        int bk = k0 & 1023;
        uint32_t abase = sb + buf * HBUF;
        uint32_t bbase = abase + 16384;
#pragma unroll
        for (int i = 0; i < 4; i++) {
            int idx = tid + 256 * i;        // 0..1023 16B units
            int r = idx >> 3, c = idx & 7;
            uint32_t off = (uint32_t)(r * 128 + ((c ^ (r & 7)) * 16));
            const __half* gp = Ah + (size_t)(bm + r) * 2048 + k0 + c * 8;
            asm volatile("cp.async.cg.shared.global [%0], [%1], 16;"
                         :: "r"(abase + off), "l"(gp));
        }
#pragma unroll
        for (int i = 0; i < 4; i++) {
            int idx = tid + 256 * i;
            int r = idx >> 3, c = idx & 7;
            uint32_t off = (uint32_t)(r * 128 + ((c ^ (r & 7)) * 16));
            const __half* gp = Bh + (size_t)(bn + r) * 1024 + bk + c * 8;
            asm volatile("cp.async.cg.shared.global [%0], [%1], 16;"
                         :: "r"(bbase + off), "l"(gp));
        }
        asm volatile("cp.async.commit_group;" ::: "memory");
    };

    const int NCH = 2048 / 64;  // 32
    issue(0, 0);

    for (int ch = 0; ch < NCH; ch++) {
        int b = ch & 1;
        if (ch + 1 < NCH) {
            issue(ch + 1, b ^ 1);
            asm volatile("cp.async.wait_group 1;" ::: "memory");
        } else {
            asm volatile("cp.async.wait_group 0;" ::: "memory");
        }
        __syncthreads();

        uint32_t abase = sb + b * HBUF;
        uint32_t bbase = abase + 16384;
#pragma unroll
        for (int ks = 0; ks < 4; ks++) {
            uint32_t afr[4][4];
#pragma unroll
            for (int mi = 0; mi < 4; mi++) {
                int r = wm + mi * 16 + (lane & 15);
                int cu = ks * 2 + (lane >> 4);
                uint32_t addr = abase + r * 128 + ((cu ^ (r & 7)) * 16);
                ldsm4(afr[mi], addr);
            }
            uint32_t bfr[2][4];
#pragma unroll
            for (int p = 0; p < 2; p++) {
                int r = wn + p * 16 + (lane & 7) + ((lane >> 4) * 8);
                int cu = ks * 2 + ((lane >> 3) & 1);
                uint32_t addr = bbase + r * 128 + ((cu ^ (r & 7)) * 16);
                ldsm4(bfr[p], addr);
            }
#pragma unroll
            for (int mi = 0; mi < 4; mi++)
#pragma unroll
                for (int nj = 0; nj < 4; nj++)
                    mma16816(acc[mi][nj], afr[mi],
                             bfr[nj >> 1][(nj & 1) * 2 + 0],
                             bfr[nj >> 1][(nj & 1) * 2 + 1]);
        }
        __syncthreads();  // all reads of buffer b done before it is refilled
    }

    // epilogue
#pragma unroll
    for (int mi = 0; mi < 4; mi++) {
#pragma unroll
        for (int nj = 0; nj < 4; nj++) {
            int row = bm + wm + mi * 16 + (lane >> 2);
            int col = bn + wn + nj * 8 + (lane & 3) * 2;
            float2 v0 = make_float2(acc[mi][nj][0], acc[mi][nj][1]);
            float2 v1 = make_float2(acc[mi][nj][2], acc[mi][nj][3]);
            *(float2*)(C + (size_t)row * V_DIM + col) = v0;
            *(float2*)(C + (size_t)(row + 8) * V_DIM + col) = v1;
        }
    }
}

// ---------------------------------------------------------------------------
// Embedding gather + pos add
// ---------------------------------------------------------------------------
__global__ void embed_kernel(const int* __restrict__ ids,
                             const float* __restrict__ emb,
                             const float* __restrict__ pos,
                             float* __restrict__ x) {
    int s = blockIdx.x;
    int q = threadIdx.x;
    int id = ids[s];
    float4 e = ((const float4*)(emb + (size_t)id * D_DIM))[q];
    float4 p = ((const float4*)(pos + (size_t)(s & 1023) * D_DIM))[q];
    float4 o;
    o.x = e.x + p.x; o.y = e.y + p.y; o.z = e.z + p.z; o.w = e.w + p.w;
    ((float4*)(x + (size_t)s * D_DIM))[q] = o;
}

// ---------------------------------------------------------------------------
// Generic fp32 GEMM (fan_out / fan_in)
// ---------------------------------------------------------------------------
template <int TB>
__global__ __launch_bounds__(256) void gemm_f32(
    const float* __restrict__ A, const float* __restrict__ Bm,
    const float* __restrict__ bias, float* __restrict__ C,
    int M, int N, int K) {
    __shared__ float As[8][128];
    __shared__ float Bs[8][128];
    const int tid = threadIdx.x;
    const int bm = blockIdx.x * 128;
    const int bn = blockIdx.y * 128;
    const int tx = tid & 15, ty = tid >> 4;
    const int mt = ty * 8, nt = tx * 8;
    float acc[8][8] = {};
    const int ar = tid >> 1, ak = (tid & 1) * 4;
    int bk, bn2;
    if (TB == 0) { bk = tid >> 5; bn2 = (tid & 31) * 4; }
    else         { bk = (tid & 1) * 4; bn2 = tid >> 1; }

    for (int k0 = 0; k0 < K; k0 += 8) {
        float4 av = *(const float4*)(A + (size_t)(bm + ar) * K + k0 + ak);
        As[ak + 0][ar] = av.x; As[ak + 1][ar] = av.y;
        As[ak + 2][ar] = av.z; As[ak + 3][ar] = av.w;
        if (TB == 0) {
            float4 bv = *(const float4*)(Bm + (size_t)(k0 + bk) * N + bn + bn2);
            *(float4*)&Bs[bk][bn2] = bv;
        } else {
            float4 bv = *(const float4*)(Bm + (size_t)(bn + bn2) * K + k0 + bk);
            Bs[bk + 0][bn2] = bv.x; Bs[bk + 1][bn2] = bv.y;
            Bs[bk + 2][bn2] = bv.z; Bs[bk + 3][bn2] = bv.w;
        }
        __syncthreads();
#pragma unroll
        for (int kk = 0; kk < 8; kk++) {
            float ra[8], rb[8];
            *(float4*)&ra[0] = *(const float4*)&As[kk][mt];
            *(float4*)&ra[4] = *(const float4*)&As[kk][mt + 4];
            *(float4*)&rb[0] = *(const float4*)&Bs[kk][nt];
            *(float4*)&rb[4] = *(const float4*)&Bs[kk][nt + 4];
#pragma unroll
            for (int i = 0; i < 8; i++)
#pragma unroll
                for (int j = 0; j < 8; j++)
                    acc[i][j] = fmaf(ra[i], rb[j], acc[i][j]);
        }
        __syncthreads();
    }
    float bv[8];
#pragma unroll
    for (int j = 0; j < 8; j++) bv[j] = bias ? bias[bn + nt + j] : 0.0f;
#pragma unroll
    for (int i = 0; i < 8; i++) {
        float* crow = C + (size_t)(bm + mt + i) * N + bn + nt;
        float4 v0, v1;
        v0.x = acc[i][0] + bv[0]; v0.y = acc[i][1] + bv[1];
        v0.z = acc[i][2] + bv[2]; v0.w = acc[i][3] + bv[3];
        v1.x = acc[i][4] + bv[4]; v1.y = acc[i][5] + bv[5];
        v1.z = acc[i][6] + bv[6]; v1.w = acc[i][7] + bv[7];
        *(float4*)crow = v0;
        *(float4*)(crow + 4) = v1;
    }
}

// ---------------------------------------------------------------------------
// Z pass
// ---------------------------------------------------------------------------
__global__ void zpass_kernel(const float* __restrict__ xb,
                             const float* __restrict__ Wz,
                             float* __restrict__ zhat,
                             float* __restrict__ pcm, int r) {
    __shared__ float zs[64];
    __shared__ float red[64];
    const int st = blockIdx.x;
    const int t = st & 7;
    const int d = threadIdx.x;
    const float* xp = xb + (size_t)st * 256;
    float z = 0.25f * (xp[d] + xp[64 + d] + xp[128 + d] + xp[192 + d]);
    zs[d] = z;
    float sq = 0.0f;
    if (r > 0) {
        float diff = zhat[(size_t)st * 64 + d] - z;
        sq = diff * diff;
    }
    __syncthreads();
    const float* wz = Wz + t * 4096;
    float acc = 0.0f;
#pragma unroll
    for (int k = 0; k < 64; k++) acc = fmaf(zs[k], wz[k * 64 + d], acc);
    red[d] = sq;
    __syncthreads();
    for (int o = 32; o > 0; o >>= 1) {
        if (d < o) red[d] += red[d + o];
        __syncthreads();
    }
    if (r > 0 && d == 0) pcm[(size_t)(r - 1) * (S_TOT * NB) + st] = red[0];
    zhat[(size_t)st * 64 + d] = acc;
}

// ---------------------------------------------------------------------------
// Fused refine MLP
// ---------------------------------------------------------------------------
__global__ __launch_bounds__(256) void mlp_kernel(
    float* __restrict__ xb, const float* __restrict__ W1,
    const float* __restrict__ W2, const float* __restrict__ lam_logit, int r) {
    extern __shared__ float sm[];
    float* Xs  = sm;                  // [64][68]
    float* W1s = Xs + 64 * 68;        // [64][256]
    float* W2s = W1s + 64 * 256;      // [256][64]
    float* Hs  = W2s + 256 * 64;      // [256][65]
    const int tid = threadIdx.x;
    const int t = blockIdx.y;
    const int rt = blockIdx.x;
    float lam = 1.0f;
    if (r > 0) lam = 1.0f / (1.0f + expf(-lam_logit[0]));

#pragma unroll
    for (int it = 0; it < 4; it++) {
        int idx = tid + 256 * it;
        int lr = idx >> 4;
        int q  = idx & 15;
        int g = rt * 64 + lr;
        int s = g >> 2, c = g & 3;
        float4 v = *(const float4*)(xb + (size_t)(s * 32 + t * 4 + c) * 64 + q * 4);
        Xs[(q * 4 + 0) * 68 + lr] = v.x;
        Xs[(q * 4 + 1) * 68 + lr] = v.y;
        Xs[(q * 4 + 2) * 68 + lr] = v.z;
        Xs[(q * 4 + 3) * 68 + lr] = v.w;
    }
    const float4* w1g = (const float4*)(W1 + (size_t)t * 64 * 256);
    const float4* w2g = (const float4*)(W2 + (size_t)t * 256 * 64);
    float4* w1s4 = (float4*)W1s;
    float4* w2s4 = (float4*)W2s;
#pragma unroll
    for (int it = 0; it < 16; it++) {
        w1s4[tid + 256 * it] = w1g[tid + 256 * it];
        w2s4[tid + 256 * it] = w2g[tid + 256 * it];
    }
    __syncthreads();

    {
        const int tx = tid & 31, ty = tid >> 5;
        const int n0 = tx * 8, m0 = ty * 8;
        float acc[8][8] = {};
        for (int k = 0; k < 64; k++) {
            float ra[8], rb[8];
            *(float4*)&ra[0] = *(const float4*)&Xs[k * 68 + m0];
            *(float4*)&ra[4] = *(const float4*)&Xs[k * 68 + m0 + 4];
            *(float4*)&rb[0] = *(const float4*)&W1s[k * 256 + n0];
            *(float4*)&rb[4] = *(const float4*)&W1s[k * 256 + n0 + 4];
#pragma unroll
            for (int i = 0; i < 8; i++)
#pragma unroll
                for (int j = 0; j < 8; j++)
                    acc[i][j] = fmaf(ra[i], rb[j], acc[i][j]);
        }
#pragma unroll
        for (int j = 0; j < 8; j++)
#pragma unroll
            for (int i = 0; i < 8; i++) {
                float v = acc[i][j];
                float u = 0.7978845608028654f * (v + 0.044715f * v * v * v);
                Hs[(n0 + j) * 65 + m0 + i] = 0.5f * v * (1.0f + tanhf(u));
            }
    }
    __syncthreads();

    {
        const int tx = tid & 15, ty = tid >> 4;
        const int n0 = tx * 4, m0 = ty * 4;
        float acc[4][4] = {};
        for (int k = 0; k < 256; k++) {
            float ra[4], rb[4];
            ra[0] = Hs[k * 65 + m0 + 0];
            ra[1] = Hs[k * 65 + m0 + 1];
            ra[2] = Hs[k * 65 + m0 + 2];
            ra[3] = Hs[k * 65 + m0 + 3];
            *(float4*)&rb[0] = *(const float4*)&W2s[k * 64 + n0];
#pragma unroll
            for (int i = 0; i < 4; i++)
#pragma unroll
                for (int j = 0; j < 4; j++)
                    acc[i][j] = fmaf(ra[i], rb[j], acc[i][j]);
        }
#pragma unroll
        for (int i = 0; i < 4; i++) {
            int g = rt * 64 + m0 + i;
            int s = g >> 2, c = g & 3;
            float* p = xb + (size_t)(s * 32 + t * 4 + c) * 64 + n0;
            float4 old = *(const float4*)p;
            old.x += lam * acc[i][0];
            old.y += lam * acc[i][1];
            old.z += lam * acc[i][2];
            old.w += lam * acc[i][3];
            *(float4*)p = old;
        }
    }
}

// ---------------------------------------------------------------------------
// LayerNorm (in place)
// ---------------------------------------------------------------------------
__global__ void ln_kernel(float* __restrict__ x, const float* __restrict__ g,
                          const float* __restrict__ b) {
    __shared__ float red[256];
    const int s = blockIdx.x, tid = threadIdx.x;
    float4* row = (float4*)(x + (size_t)s * D_DIM);
    float4 v = row[tid];
    red[tid] = v.x + v.y + v.z + v.w;
    __syncthreads();
    for (int o = 128; o > 0; o >>= 1) {
        if (tid < o) red[tid] += red[tid + o];
        __syncthreads();
    }
    float mu = red[0] * (1.0f / 1024.0f);
    __syncthreads();
    float dx = v.x - mu, dy = v.y - mu, dz = v.z - mu, dw = v.w - mu;
    red[tid] = dx * dx + dy * dy + dz * dz + dw * dw;
    __syncthreads();
    for (int o = 128; o > 0; o >>= 1) {
        if (tid < o) red[tid] += red[tid + o];
        __syncthreads();
    }
    float rstd = rsqrtf(red[0] * (1.0f / 1024.0f) + 1e-5f);
    float4 gg = ((const float4*)g)[tid];
    float4 bb = ((const float4*)b)[tid];
    float4 o4;
    o4.x = dx * rstd * gg.x + bb.x;
    o4.y = dy * rstd * gg.y + bb.y;
    o4.z = dz * rstd * gg.z + bb.z;
    o4.w = dw * rstd * gg.w + bb.w;
    row[tid] = o4;
}

// ---------------------------------------------------------------------------
// Deterministic aux reduction
// ---------------------------------------------------------------------------
__global__ void aux_kernel(const float* __restrict__ pcm, float* __restrict__ out) {
    __shared__ float red[256];
    const int tid = threadIdx.x;
    float s = 0.0f;
    for (int i = tid; i < 2 * S_TOT * NB; i += 256) s += pcm[i];
    red[tid] = s;
    __syncthreads();
    for (int o = 128; o > 0; o >>= 1) {
        if (tid < o) red[tid] += red[tid + o];
        __syncthreads();
    }
    if (tid == 0) out[0] = 0.1f * red[0] / 262144.0f;
}

// ---------------------------------------------------------------------------
extern "C" void kernel_launch(void* const* d_in, const int* in_sizes, int n_in,
                              void* d_out, int out_size) {
    const int*   ids  = (const int*)d_in[0];
    const float* emb  = (const float*)d_in[1];
    const float* pos  = (const float*)d_in[2];
    const float* fo_w = (const float*)d_in[3];
    const float* fo_b = (const float*)d_in[4];
    const float* W1   = (const float*)d_in[5];
    const float* W2   = (const float*)d_in[6];
    const float* Wz   = (const float*)d_in[7];
    const float* fi_w = (const float*)d_in[8];
    const float* fi_b = (const float*)d_in[9];
    const float* ln_g = (const float*)d_in[10];
    const float* ln_b = (const float*)d_in[11];
    const float* lamp = (const float*)d_in[12];
    float* out = (float*)d_out;

    float *x, *xb, *zhat, *pcm;
    __half *Ah, *Bh;
    cudaGetSymbolAddress((void**)&x,    g_x);
    cudaGetSymbolAddress((void**)&xb,   g_xb);
    cudaGetSymbolAddress((void**)&zhat, g_zhat);
    cudaGetSymbolAddress((void**)&pcm,  g_pcm);
    cudaGetSymbolAddress((void**)&Ah,   g_Ah);
    cudaGetSymbolAddress((void**)&Bh,   g_Bh);

    const int MLP_SMEM = (64 * 68 + 64 * 256 + 256 * 64 + 256 * 65) * 4;
    cudaFuncSetAttribute(mlp_kernel, cudaFuncAttributeMaxDynamicSharedMemorySize,
                         MLP_SMEM);
    cudaFuncSetAttribute(gemm_hmma, cudaFuncAttributeMaxDynamicSharedMemorySize,
                         HSMEM);

    // 1. embed + B fp16 conversion (independent)
    embed_kernel<<<S_TOT, 256>>>(ids, emb, pos, x);
    convB_h<<<V_DIM, 256>>>(emb, Bh);

    // 2. fan_out
    gemm_f32<0><<<dim3(S_TOT / 128, T_DIM / 128), 256>>>(x, fo_w, fo_b, xb,
                                                         S_TOT, T_DIM, D_DIM);

    // 3. refine passes
    for (int r = 0; r < 3; r++) {
        zpass_kernel<<<S_TOT * NB, 64>>>(xb, Wz, zhat, pcm, r);
        mlp_kernel<<<dim3(256, NB), 256, MLP_SMEM>>>(xb, W1, W2, lamp, r);
    }

    // 4. fan_in
    gemm_f32<0><<<dim3(S_TOT / 128, D_DIM / 128), 256>>>(xb, fi_w, fi_b, x,
                                                         S_TOT, D_DIM, T_DIM);

    // 5. layernorm (in place)
    ln_kernel<<<S_TOT, 256>>>(x, ln_g, ln_b);

    // 6. A fp16 split + HMMA logits GEMM (M fast-varying for B L2 reuse)
    convA_h<<<S_TOT, 256>>>(x, Ah);
    gemm_hmma<<<dim3(S_TOT / 128, V_DIM / 128), 256, HSMEM>>>(Ah, Bh, out);

    // 7. aux loss appended after logits
    if (out_size > S_TOT * V_DIM) {
        aux_kernel<<<1, 256>>>(pcm, out + (size_t)S_TOT * V_DIM);
    }
}

// round 5
// speedup vs baseline: 3.2036x; 1.2304x over previous
#include <cuda_runtime.h>
#include <cuda_fp16.h>
#include <stdint.h>
#include <math.h>

// Problem dims
#define S_TOT 4096     // BS*N
#define D_DIM 1024
#define T_DIM 2048
#define V_DIM 32000
#define NB 8

// Scratch (device globals — allocation-free rule)
__device__ float g_x[S_TOT * D_DIM];        // 16 MB
__device__ float g_xb[S_TOT * T_DIM];       // 32 MB
__device__ float g_zhat[S_TOT * NB * 64];   // 8 MB
__device__ float g_pcm[2 * S_TOT * NB];
__device__ __half g_Ah[(size_t)S_TOT * 2048];    // 16 MB: logits A 2-term split
__device__ __half g_Bh[(size_t)V_DIM * 1024];    // 65 MB: emb fp16
__device__ __half g_Axo[(size_t)S_TOT * 3072];   // 25 MB: fan_out A 3-term
__device__ __half g_Bfo[(size_t)T_DIM * 3072];   // 12.6 MB: fo_w^T 3-term
__device__ __half g_Axi[(size_t)S_TOT * 6144];   // 50 MB: fan_in A 3-term
__device__ __half g_Bfi[(size_t)D_DIM * 6144];   // 12.6 MB: fi_w^T 3-term

__device__ __forceinline__ uint32_t smem_u32(const void* p) {
    uint32_t a;
    asm("{ .reg .u64 t; cvta.to.shared.u64 t, %1; cvt.u32.u64 %0, t; }"
        : "=r"(a) : "l"(p));
    return a;
}

// ---------------------------------------------------------------------------
// Conversions
// ---------------------------------------------------------------------------
// A 2-term (hi | lo), row length 1024 -> 2048 (logits path)
__global__ void convA_h(const float* __restrict__ x, __half* __restrict__ Ah) {
    int row = blockIdx.x;
    int q = threadIdx.x;
    float4 v = ((const float4*)(x + (size_t)row * 1024))[q];
    __half h0 = __float2half_rn(v.x), h1 = __float2half_rn(v.y);
    __half h2 = __float2half_rn(v.z), h3 = __float2half_rn(v.w);
    __half l0 = __float2half_rn(v.x - __half2float(h0));
    __half l1 = __float2half_rn(v.y - __half2float(h1));
    __half l2 = __float2half_rn(v.z - __half2float(h2));
    __half l3 = __float2half_rn(v.w - __half2float(h3));
    uint2 H, L;
    H.x = (uint32_t)__half_as_ushort(h0) | ((uint32_t)__half_as_ushort(h1) << 16);
    H.y = (uint32_t)__half_as_ushort(h2) | ((uint32_t)__half_as_ushort(h3) << 16);
    L.x = (uint32_t)__half_as_ushort(l0) | ((uint32_t)__half_as_ushort(l1) << 16);
    L.y = (uint32_t)__half_as_ushort(l2) | ((uint32_t)__half_as_ushort(l3) << 16);
    __half* base = Ah + (size_t)row * 2048 + q * 4;
    *(uint2*)base = H;
    *(uint2*)(base + 1024) = L;
}

// B plain fp16 (logits)
__global__ void convB_h(const float* __restrict__ emb, __half* __restrict__ Bh) {
    size_t i = (size_t)blockIdx.x * 256 + threadIdx.x;
    float4 v = ((const float4*)emb)[i];
    uint2 H;
    H.x = (uint32_t)__half_as_ushort(__float2half_rn(v.x)) |
          ((uint32_t)__half_as_ushort(__float2half_rn(v.y)) << 16);
    H.y = (uint32_t)__half_as_ushort(__float2half_rn(v.z)) |
          ((uint32_t)__half_as_ushort(__float2half_rn(v.w)) << 16);
    ((uint2*)Bh)[i] = H;
}

// A 3-term (hi | lo | hi), row length K -> 3K
__global__ void convA3(const float* __restrict__ src, __half* __restrict__ dst,
                       int K) {
    int row = blockIdx.x;
    const float4* sp = (const float4*)(src + (size_t)row * K);
    __half* base = dst + (size_t)row * 3 * K;
    for (int q = threadIdx.x; q < K / 4; q += 256) {
        float4 v = sp[q];
        __half h0 = __float2half_rn(v.x), h1 = __float2half_rn(v.y);
        __half h2 = __float2half_rn(v.z), h3 = __float2half_rn(v.w);
        __half l0 = __float2half_rn(v.x - __half2float(h0));
        __half l1 = __float2half_rn(v.y - __half2float(h1));
        __half l2 = __float2half_rn(v.z - __half2float(h2));
        __half l3 = __float2half_rn(v.w - __half2float(h3));
        uint2 H, L;
        H.x = (uint32_t)__half_as_ushort(h0) | ((uint32_t)__half_as_ushort(h1) << 16);
        H.y = (uint32_t)__half_as_ushort(h2) | ((uint32_t)__half_as_ushort(h3) << 16);
        L.x = (uint32_t)__half_as_ushort(l0) | ((uint32_t)__half_as_ushort(l1) << 16);
        L.y = (uint32_t)__half_as_ushort(l2) | ((uint32_t)__half_as_ushort(l3) << 16);
        *(uint2*)(base + q * 4)         = H;
        *(uint2*)(base + K + q * 4)     = L;
        *(uint2*)(base + 2 * K + q * 4) = H;
    }
}

// B transpose + 3-term (hi | hi | lo): src [K,N] row-major -> dst [N, 3K]
__global__ void convB3T(const float* __restrict__ src, __half* __restrict__ dst,
                        int K, int N) {
    __shared__ float tile[32][33];
    int k0 = blockIdx.x * 32, n0 = blockIdx.y * 32;
    int tx = threadIdx.x & 31, ty = threadIdx.x >> 5;  // ty 0..7
    for (int i = ty; i < 32; i += 8)
        tile[i][tx] = src[(size_t)(k0 + i) * N + n0 + tx];
    __syncthreads();
    for (int i = ty; i < 32; i += 8) {
        int n = n0 + i;
        float v = tile[tx][i];  // src[k0+tx][n]
        __half h = __float2half_rn(v);
        __half l = __float2half_rn(v - __half2float(h));
        __half* row = dst + (size_t)n * 3 * K + k0 + tx;
        row[0]     = h;
        row[K]     = h;
        row[2 * K] = l;
    }
}

// ---------------------------------------------------------------------------
// HMMA fp16 GEMM: C[M,N] = A[M,ldA-k'] @ B[N,ldB]^T (+bias)
// B k-index wraps at (bkmask+1). CTA 128x128, 8 warps, cp.async dbl buffer.
// ---------------------------------------------------------------------------
#define HBUF 32768
#define HSMEM (2 * HBUF)

__device__ __forceinline__ void ldsm4(uint32_t* r, uint32_t addr) {
    asm volatile("ldmatrix.sync.aligned.m8n8.x4.shared.b16 {%0,%1,%2,%3}, [%4];"
                 : "=r"(r[0]), "=r"(r[1]), "=r"(r[2]), "=r"(r[3]) : "r"(addr));
}
__device__ __forceinline__ void mma16816(float* c, const uint32_t* a,
                                         uint32_t b0, uint32_t b1) {
    asm volatile(
        "mma.sync.aligned.m16n8k16.row.col.f32.f16.f16.f32 "
        "{%0,%1,%2,%3}, {%4,%5,%6,%7}, {%8,%9}, {%0,%1,%2,%3};"
        : "+f"(c[0]), "+f"(c[1]), "+f"(c[2]), "+f"(c[3])
        : "r"(a[0]), "r"(a[1]), "r"(a[2]), "r"(a[3]), "r"(b0), "r"(b1));
}

__global__ __launch_bounds__(256) void gemm_hmma(
    const __half* __restrict__ A, const __half* __restrict__ B,
    const float* __restrict__ bias, float* __restrict__ C,
    int ldA, int ldB, int N, int nch, int bkmask) {
    extern __shared__ __align__(128) char smem[];
    const uint32_t sb = smem_u32(smem);
    const int tid = threadIdx.x, lane = tid & 31, wid = tid >> 5;
    const int bm = blockIdx.x * 128, bn = blockIdx.y * 128;
    const int wm = (wid & 1) * 64, wn = (wid >> 1) * 32;

    float acc[4][4][4] = {};

    auto issue = [&](int ch, int buf) {
        int k0 = ch * 64;
        int bk = k0 & bkmask;
        uint32_t abase = sb + buf * HBUF;
        uint32_t bbase = abase + 16384;
#pragma unroll
        for (int i = 0; i < 4; i++) {
            int idx = tid + 256 * i;
            int r = idx >> 3, c = idx & 7;
            uint32_t off = (uint32_t)(r * 128 + ((c ^ (r & 7)) * 16));
            const __half* gp = A + (size_t)(bm + r) * ldA + k0 + c * 8;
            asm volatile("cp.async.cg.shared.global [%0], [%1], 16;"
                         :: "r"(abase + off), "l"(gp));
        }
#pragma unroll
        for (int i = 0; i < 4; i++) {
            int idx = tid + 256 * i;
            int r = idx >> 3, c = idx & 7;
            uint32_t off = (uint32_t)(r * 128 + ((c ^ (r & 7)) * 16));
            const __half* gp = B + (size_t)(bn + r) * ldB + bk + c * 8;
            asm volatile("cp.async.cg.shared.global [%0], [%1], 16;"
                         :: "r"(bbase + off), "l"(gp));
        }
        asm volatile("cp.async.commit_group;" ::: "memory");
    };

    issue(0, 0);

    for (int ch = 0; ch < nch; ch++) {
        int b = ch & 1;
        if (ch + 1 < nch) {
            issue(ch + 1, b ^ 1);
            asm volatile("cp.async.wait_group 1;" ::: "memory");
        } else {
            asm volatile("cp.async.wait_group 0;" ::: "memory");
        }
        __syncthreads();

        uint32_t abase = sb + b * HBUF;
        uint32_t bbase = abase + 16384;
#pragma unroll
        for (int ks = 0; ks < 4; ks++) {
            uint32_t afr[4][4];
#pragma unroll
            for (int mi = 0; mi < 4; mi++) {
                int r = wm + mi * 16 + (lane & 15);
                int cu = ks * 2 + (lane >> 4);
                uint32_t addr = abase + r * 128 + ((cu ^ (r & 7)) * 16);
                ldsm4(afr[mi], addr);
            }
            uint32_t bfr[2][4];
#pragma unroll
            for (int p = 0; p < 2; p++) {
                int r = wn + p * 16 + (lane & 7) + ((lane >> 4) * 8);
                int cu = ks * 2 + ((lane >> 3) & 1);
                uint32_t addr = bbase + r * 128 + ((cu ^ (r & 7)) * 16);
                ldsm4(bfr[p], addr);
            }
#pragma unroll
            for (int mi = 0; mi < 4; mi++)
#pragma unroll
                for (int nj = 0; nj < 4; nj++)
                    mma16816(acc[mi][nj], afr[mi],
                             bfr[nj >> 1][(nj & 1) * 2 + 0],
                             bfr[nj >> 1][(nj & 1) * 2 + 1]);
        }
        __syncthreads();
    }

    // epilogue (+bias)
#pragma unroll
    for (int mi = 0; mi < 4; mi++) {
#pragma unroll
        for (int nj = 0; nj < 4; nj++) {
            int row = bm + wm + mi * 16 + (lane >> 2);
            int col = bn + wn + nj * 8 + (lane & 3) * 2;
            float b0 = bias ? bias[col] : 0.0f;
            float b1 = bias ? bias[col + 1] : 0.0f;
            float2 v0 = make_float2(acc[mi][nj][0] + b0, acc[mi][nj][1] + b1);
            float2 v1 = make_float2(acc[mi][nj][2] + b0, acc[mi][nj][3] + b1);
            *(float2*)(C + (size_t)row * N + col) = v0;
            *(float2*)(C + (size_t)(row + 8) * N + col) = v1;
        }
    }
}

// ---------------------------------------------------------------------------
// Embedding gather + pos add
// ---------------------------------------------------------------------------
__global__ void embed_kernel(const int* __restrict__ ids,
                             const float* __restrict__ emb,
                             const float* __restrict__ pos,
                             float* __restrict__ x) {
    int s = blockIdx.x;
    int q = threadIdx.x;
    int id = ids[s];
    float4 e = ((const float4*)(emb + (size_t)id * D_DIM))[q];
    float4 p = ((const float4*)(pos + (size_t)(s & 1023) * D_DIM))[q];
    float4 o;
    o.x = e.x + p.x; o.y = e.y + p.y; o.z = e.z + p.z; o.w = e.w + p.w;
    ((float4*)(x + (size_t)s * D_DIM))[q] = o;
}

// ---------------------------------------------------------------------------
// Z pass
// ---------------------------------------------------------------------------
__global__ void zpass_kernel(const float* __restrict__ xb,
                             const float* __restrict__ Wz,
                             float* __restrict__ zhat,
                             float* __restrict__ pcm, int r) {
    __shared__ float zs[64];
    __shared__ float red[64];
    const int st = blockIdx.x;
    const int t = st & 7;
    const int d = threadIdx.x;
    const float* xp = xb + (size_t)st * 256;
    float z = 0.25f * (xp[d] + xp[64 + d] + xp[128 + d] + xp[192 + d]);
    zs[d] = z;
    float sq = 0.0f;
    if (r > 0) {
        float diff = zhat[(size_t)st * 64 + d] - z;
        sq = diff * diff;
    }
    __syncthreads();
    const float* wz = Wz + t * 4096;
    float acc = 0.0f;
#pragma unroll
    for (int k = 0; k < 64; k++) acc = fmaf(zs[k], wz[k * 64 + d], acc);
    red[d] = sq;
    __syncthreads();
    for (int o = 32; o > 0; o >>= 1) {
        if (d < o) red[d] += red[d + o];
        __syncthreads();
    }
    if (r > 0 && d == 0) pcm[(size_t)(r - 1) * (S_TOT * NB) + st] = red[0];
    zhat[(size_t)st * 64 + d] = acc;
}

// ---------------------------------------------------------------------------
// Fused refine MLP (fp32)
// ---------------------------------------------------------------------------
__global__ __launch_bounds__(256) void mlp_kernel(
    float* __restrict__ xb, const float* __restrict__ W1,
    const float* __restrict__ W2, const float* __restrict__ lam_logit, int r) {
    extern __shared__ float sm[];
    float* Xs  = sm;                  // [64][68]
    float* W1s = Xs + 64 * 68;        // [64][256]
    float* W2s = W1s + 64 * 256;      // [256][64]
    float* Hs  = W2s + 256 * 64;      // [256][65]
    const int tid = threadIdx.x;
    const int t = blockIdx.y;
    const int rt = blockIdx.x;
    float lam = 1.0f;
    if (r > 0) lam = 1.0f / (1.0f + expf(-lam_logit[0]));

#pragma unroll
    for (int it = 0; it < 4; it++) {
        int idx = tid + 256 * it;
        int lr = idx >> 4;
        int q  = idx & 15;
        int g = rt * 64 + lr;
        int s = g >> 2, c = g & 3;
        float4 v = *(const float4*)(xb + (size_t)(s * 32 + t * 4 + c) * 64 + q * 4);
        Xs[(q * 4 + 0) * 68 + lr] = v.x;
        Xs[(q * 4 + 1) * 68 + lr] = v.y;
        Xs[(q * 4 + 2) * 68 + lr] = v.z;
        Xs[(q * 4 + 3) * 68 + lr] = v.w;
    }
    const float4* w1g = (const float4*)(W1 + (size_t)t * 64 * 256);
    const float4* w2g = (const float4*)(W2 + (size_t)t * 256 * 64);
    float4* w1s4 = (float4*)W1s;
    float4* w2s4 = (float4*)W2s;
#pragma unroll
    for (int it = 0; it < 16; it++) {
        w1s4[tid + 256 * it] = w1g[tid + 256 * it];
        w2s4[tid + 256 * it] = w2g[tid + 256 * it];
    }
    __syncthreads();

    {
        const int tx = tid & 31, ty = tid >> 5;
        const int n0 = tx * 8, m0 = ty * 8;
        float acc[8][8] = {};
        for (int k = 0; k < 64; k++) {
            float ra[8], rb[8];
            *(float4*)&ra[0] = *(const float4*)&Xs[k * 68 + m0];
            *(float4*)&ra[4] = *(const float4*)&Xs[k * 68 + m0 + 4];
            *(float4*)&rb[0] = *(const float4*)&W1s[k * 256 + n0];
            *(float4*)&rb[4] = *(const float4*)&W1s[k * 256 + n0 + 4];
#pragma unroll
            for (int i = 0; i < 8; i++)
#pragma unroll
                for (int j = 0; j < 8; j++)
                    acc[i][j] = fmaf(ra[i], rb[j], acc[i][j]);
        }
#pragma unroll
        for (int j = 0; j < 8; j++)
#pragma unroll
            for (int i = 0; i < 8; i++) {
                float v = acc[i][j];
                float u = 0.7978845608028654f * (v + 0.044715f * v * v * v);
                Hs[(n0 + j) * 65 + m0 + i] = 0.5f * v * (1.0f + tanhf(u));
            }
    }
    __syncthreads();

    {
        const int tx = tid & 15, ty = tid >> 4;
        const int n0 = tx * 4, m0 = ty * 4;
        float acc[4][4] = {};
        for (int k = 0; k < 256; k++) {
            float ra[4], rb[4];
            ra[0] = Hs[k * 65 + m0 + 0];
            ra[1] = Hs[k * 65 + m0 + 1];
            ra[2] = Hs[k * 65 + m0 + 2];
            ra[3] = Hs[k * 65 + m0 + 3];
            *(float4*)&rb[0] = *(const float4*)&W2s[k * 64 + n0];
#pragma unroll
            for (int i = 0; i < 4; i++)
#pragma unroll
                for (int j = 0; j < 4; j++)
                    acc[i][j] = fmaf(ra[i], rb[j], acc[i][j]);
        }
#pragma unroll
        for (int i = 0; i < 4; i++) {
            int g = rt * 64 + m0 + i;
            int s = g >> 2, c = g & 3;
            float* p = xb + (size_t)(s * 32 + t * 4 + c) * 64 + n0;
            float4 old = *(const float4*)p;
            old.x += lam * acc[i][0];
            old.y += lam * acc[i][1];
            old.z += lam * acc[i][2];
            old.w += lam * acc[i][3];
            *(float4*)p = old;
        }
    }
}

// ---------------------------------------------------------------------------
// LayerNorm (in place)
// ---------------------------------------------------------------------------
__global__ void ln_kernel(float* __restrict__ x, const float* __restrict__ g,
                          const float* __restrict__ b) {
    __shared__ float red[256];
    const int s = blockIdx.x, tid = threadIdx.x;
    float4* row = (float4*)(x + (size_t)s * D_DIM);
    float4 v = row[tid];
    red[tid] = v.x + v.y + v.z + v.w;
    __syncthreads();
    for (int o = 128; o > 0; o >>= 1) {
        if (tid < o) red[tid] += red[tid + o];
        __syncthreads();
    }
    float mu = red[0] * (1.0f / 1024.0f);
    __syncthreads();
    float dx = v.x - mu, dy = v.y - mu, dz = v.z - mu, dw = v.w - mu;
    red[tid] = dx * dx + dy * dy + dz * dz + dw * dw;
    __syncthreads();
    for (int o = 128; o > 0; o >>= 1) {
        if (tid < o) red[tid] += red[tid + o];
        __syncthreads();
    }
    float rstd = rsqrtf(red[0] * (1.0f / 1024.0f) + 1e-5f);
    float4 gg = ((const float4*)g)[tid];
    float4 bb = ((const float4*)b)[tid];
    float4 o4;
    o4.x = dx * rstd * gg.x + bb.x;
    o4.y = dy * rstd * gg.y + bb.y;
    o4.z = dz * rstd * gg.z + bb.z;
    o4.w = dw * rstd * gg.w + bb.w;
    row[tid] = o4;
}

// ---------------------------------------------------------------------------
// Deterministic aux reduction
// ---------------------------------------------------------------------------
__global__ void aux_kernel(const float* __restrict__ pcm, float* __restrict__ out) {
    __shared__ float red[256];
    const int tid = threadIdx.x;
    float s = 0.0f;
    for (int i = tid; i < 2 * S_TOT * NB; i += 256) s += pcm[i];
    red[tid] = s;
    __syncthreads();
    for (int o = 128; o > 0; o >>= 1) {
        if (tid < o) red[tid] += red[tid + o];
        __syncthreads();
    }
    if (tid == 0) out[0] = 0.1f * red[0] / 262144.0f;
}

// ---------------------------------------------------------------------------
extern "C" void kernel_launch(void* const* d_in, const int* in_sizes, int n_in,
                              void* d_out, int out_size) {
    const int*   ids  = (const int*)d_in[0];
    const float* emb  = (const float*)d_in[1];
    const float* pos  = (const float*)d_in[2];
    const float* fo_w = (const float*)d_in[3];
    const float* fo_b = (const float*)d_in[4];
    const float* W1   = (const float*)d_in[5];
    const float* W2   = (const float*)d_in[6];
    const float* Wz   = (const float*)d_in[7];
    const float* fi_w = (const float*)d_in[8];
    const float* fi_b = (const float*)d_in[9];
    const float* ln_g = (const float*)d_in[10];
    const float* ln_b = (const float*)d_in[11];
    const float* lamp = (const float*)d_in[12];
    float* out = (float*)d_out;

    float *x, *xb, *zhat, *pcm;
    __half *Ah, *Bh, *Axo, *Bfo, *Axi, *Bfi;
    cudaGetSymbolAddress((void**)&x,    g_x);
    cudaGetSymbolAddress((void**)&xb,   g_xb);
    cudaGetSymbolAddress((void**)&zhat, g_zhat);
    cudaGetSymbolAddress((void**)&pcm,  g_pcm);
    cudaGetSymbolAddress((void**)&Ah,   g_Ah);
    cudaGetSymbolAddress((void**)&Bh,   g_Bh);
    cudaGetSymbolAddress((void**)&Axo,  g_Axo);
    cudaGetSymbolAddress((void**)&Bfo,  g_Bfo);
    cudaGetSymbolAddress((void**)&Axi,  g_Axi);
    cudaGetSymbolAddress((void**)&Bfi,  g_Bfi);

    const int MLP_SMEM = (64 * 68 + 64 * 256 + 256 * 64 + 256 * 65) * 4;
    cudaFuncSetAttribute(mlp_kernel, cudaFuncAttributeMaxDynamicSharedMemorySize,
                         MLP_SMEM);
    cudaFuncSetAttribute(gemm_hmma, cudaFuncAttributeMaxDynamicSharedMemorySize,
                         HSMEM);

    // 1. embed + weight conversions (order keeps independent work early)
    embed_kernel<<<S_TOT, 256>>>(ids, emb, pos, x);
    convB_h<<<V_DIM, 256>>>(emb, Bh);
    convB3T<<<dim3(D_DIM / 32, T_DIM / 32), 256>>>(fo_w, Bfo, D_DIM, T_DIM);
    convB3T<<<dim3(T_DIM / 32, D_DIM / 32), 256>>>(fi_w, Bfi, T_DIM, D_DIM);

    // 2. fan_out (HMMA 3-term): xb = x @ fo_w + fo_b
    convA3<<<S_TOT, 256>>>(x, Axo, D_DIM);
    gemm_hmma<<<dim3(S_TOT / 128, T_DIM / 128), 256, HSMEM>>>(
        Axo, Bfo, fo_b, xb, 3 * D_DIM, 3 * D_DIM, T_DIM, 3 * D_DIM / 64, ~0);

    // 3. refine passes
    for (int r = 0; r < 3; r++) {
        zpass_kernel<<<S_TOT * NB, 64>>>(xb, Wz, zhat, pcm, r);
        mlp_kernel<<<dim3(256, NB), 256, MLP_SMEM>>>(xb, W1, W2, lamp, r);
    }

    // 4. fan_in (HMMA 3-term): x = xb @ fi_w + fi_b
    convA3<<<S_TOT, 256>>>(xb, Axi, T_DIM);
    gemm_hmma<<<dim3(S_TOT / 128, D_DIM / 128), 256, HSMEM>>>(
        Axi, Bfi, fi_b, x, 3 * T_DIM, 3 * T_DIM, D_DIM, 3 * T_DIM / 64, ~0);

    // 5. layernorm (in place)
    ln_kernel<<<S_TOT, 256>>>(x, ln_g, ln_b);

    // 6. logits (HMMA 2-term A-split, B k-wrap at 1024)
    convA_h<<<S_TOT, 256>>>(x, Ah);
    gemm_hmma<<<dim3(S_TOT / 128, V_DIM / 128), 256, HSMEM>>>(
        Ah, Bh, (const float*)0, out, 2048, 1024, V_DIM, 32, 1023);

    // 7. aux loss appended after logits
    if (out_size > S_TOT * V_DIM) {
        aux_kernel<<<1, 256>>>(pcm, out + (size_t)S_TOT * V_DIM);
    }
}

// round 6
// speedup vs baseline: 4.1963x; 1.3099x over previous
#include <cuda_runtime.h>
#include <cuda_fp16.h>
#include <stdint.h>
#include <math.h>

// Problem dims
#define S_TOT 4096     // BS*N
#define D_DIM 1024
#define T_DIM 2048
#define V_DIM 32000
#define NB 8

// Scratch (device globals — allocation-free rule)
__device__ float g_x[S_TOT * D_DIM];
__device__ float g_xb[S_TOT * T_DIM];
__device__ float g_zhat[S_TOT * NB * 64];
__device__ float g_pcm[2 * S_TOT * NB];
__device__ __half g_Ah[(size_t)S_TOT * 2048];
__device__ __half g_Bh[(size_t)V_DIM * 1024];
__device__ __half g_Axo[(size_t)S_TOT * 3072];
__device__ __half g_Bfo[(size_t)T_DIM * 3072];
__device__ __half g_Axi[(size_t)S_TOT * 6144];
__device__ __half g_Bfi[(size_t)D_DIM * 6144];
__device__ __half g_W1p[NB * 256 * 64];   // pre-swizzled fp16 W1 (B-operand layout)
__device__ __half g_W2p[NB * 64 * 256];   // pre-swizzled fp16 W2

__device__ __forceinline__ uint32_t smem_u32(const void* p) {
    uint32_t a;
    asm("{ .reg .u64 t; cvta.to.shared.u64 t, %1; cvt.u32.u64 %0, t; }"
        : "=r"(a) : "l"(p));
    return a;
}
__device__ __forceinline__ void ldsm4(uint32_t* r, uint32_t addr) {
    asm volatile("ldmatrix.sync.aligned.m8n8.x4.shared.b16 {%0,%1,%2,%3}, [%4];"
                 : "=r"(r[0]), "=r"(r[1]), "=r"(r[2]), "=r"(r[3]) : "r"(addr));
}
__device__ __forceinline__ void mma16816(float* c, const uint32_t* a,
                                         uint32_t b0, uint32_t b1) {
    asm volatile(
        "mma.sync.aligned.m16n8k16.row.col.f32.f16.f16.f32 "
        "{%0,%1,%2,%3}, {%4,%5,%6,%7}, {%8,%9}, {%0,%1,%2,%3};"
        : "+f"(c[0]), "+f"(c[1]), "+f"(c[2]), "+f"(c[3])
        : "r"(a[0]), "r"(a[1]), "r"(a[2]), "r"(a[3]), "r"(b0), "r"(b1));
}
__device__ __forceinline__ float gelu_f(float v) {
    float u = 0.7978845608028654f * (v + 0.044715f * v * v * v);
    float th;
    asm("tanh.approx.f32 %0, %1;" : "=f"(th) : "f"(u));
    return 0.5f * v * (1.0f + th);
}
__device__ __forceinline__ uint32_t pack_h2(float a, float b) {
    __half ha = __float2half_rn(a), hb = __float2half_rn(b);
    return (uint32_t)__half_as_ushort(ha) | ((uint32_t)__half_as_ushort(hb) << 16);
}

// ---------------------------------------------------------------------------
// Conversions (logits / fan paths — unchanged from R5)
// ---------------------------------------------------------------------------
__global__ void convA_h(const float* __restrict__ x, __half* __restrict__ Ah) {
    int row = blockIdx.x;
    int q = threadIdx.x;
    float4 v = ((const float4*)(x + (size_t)row * 1024))[q];
    __half h0 = __float2half_rn(v.x), h1 = __float2half_rn(v.y);
    __half h2 = __float2half_rn(v.z), h3 = __float2half_rn(v.w);
    uint2 H, L;
    H.x = pack_h2(v.x, v.y); H.y = pack_h2(v.z, v.w);
    L.x = pack_h2(v.x - __half2float(h0), v.y - __half2float(h1));
    L.y = pack_h2(v.z - __half2float(h2), v.w - __half2float(h3));
    __half* base = Ah + (size_t)row * 2048 + q * 4;
    *(uint2*)base = H;
    *(uint2*)(base + 1024) = L;
}

__global__ void convB_h(const float* __restrict__ emb, __half* __restrict__ Bh) {
    size_t i = (size_t)blockIdx.x * 256 + threadIdx.x;
    float4 v = ((const float4*)emb)[i];
    uint2 H;
    H.x = pack_h2(v.x, v.y); H.y = pack_h2(v.z, v.w);
    ((uint2*)Bh)[i] = H;
}

__global__ void convA3(const float* __restrict__ src, __half* __restrict__ dst,
                       int K) {
    int row = blockIdx.x;
    const float4* sp = (const float4*)(src + (size_t)row * K);
    __half* base = dst + (size_t)row * 3 * K;
    for (int q = threadIdx.x; q < K / 4; q += 256) {
        float4 v = sp[q];
        __half h0 = __float2half_rn(v.x), h1 = __float2half_rn(v.y);
        __half h2 = __float2half_rn(v.z), h3 = __float2half_rn(v.w);
        uint2 H, L;
        H.x = pack_h2(v.x, v.y); H.y = pack_h2(v.z, v.w);
        L.x = pack_h2(v.x - __half2float(h0), v.y - __half2float(h1));
        L.y = pack_h2(v.z - __half2float(h2), v.w - __half2float(h3));
        *(uint2*)(base + q * 4)         = H;
        *(uint2*)(base + K + q * 4)     = L;
        *(uint2*)(base + 2 * K + q * 4) = H;
    }
}

__global__ void convB3T(const float* __restrict__ src, __half* __restrict__ dst,
                        int K, int N) {
    __shared__ float tile[32][33];
    int k0 = blockIdx.x * 32, n0 = blockIdx.y * 32;
    int tx = threadIdx.x & 31, ty = threadIdx.x >> 5;
    for (int i = ty; i < 32; i += 8)
        tile[i][tx] = src[(size_t)(k0 + i) * N + n0 + tx];
    __syncthreads();
    for (int i = ty; i < 32; i += 8) {
        int n = n0 + i;
        float v = tile[tx][i];
        __half h = __float2half_rn(v);
        __half l = __float2half_rn(v - __half2float(h));
        __half* row = dst + (size_t)n * 3 * K + k0 + tx;
        row[0]     = h;
        row[K]     = h;
        row[2 * K] = l;
    }
}

// Pre-swizzled fp16 weight layouts for mlp_tc (match ldsm swizzle).
// W1: [8][64(k)][256(n)] -> W1p[t][r=n][physchunk 0..7][j]: k = (ph^(r&7))*8+j
__global__ void convW1p(const float* __restrict__ W1, __half* __restrict__ W1p) {
    int idx = blockIdx.x * 256 + threadIdx.x;  // 8*16384
    int t = idx >> 14, rem = idx & 16383;
    int rr = rem >> 6, ph = (rem >> 3) & 7, j = rem & 7;
    int k = ((ph ^ (rr & 7)) << 3) | j;
    W1p[idx] = __float2half_rn(W1[((size_t)t * 64 + k) * 256 + rr]);
}
// W2: [8][256(k)][64(n)] -> W2p[t][r=n][physchunk 0..31][j]
__global__ void convW2p(const float* __restrict__ W2, __half* __restrict__ W2p) {
    int idx = blockIdx.x * 256 + threadIdx.x;  // 8*16384
    int t = idx >> 14, rem = idx & 16383;
    int rr = rem >> 8, ph = (rem >> 3) & 31, j = rem & 7;
    int c = (ph & ~7) | ((ph & 7) ^ (rr & 7));
    int k = (c << 3) | j;
    W2p[idx] = __float2half_rn(W2[((size_t)t * 256 + k) * 64 + rr]);
}

// ---------------------------------------------------------------------------
// HMMA fp16 GEMM (fan_out / fan_in / logits) — unchanged from R5
// ---------------------------------------------------------------------------
#define HBUF 32768
#define HSMEM (2 * HBUF)

__global__ __launch_bounds__(256) void gemm_hmma(
    const __half* __restrict__ A, const __half* __restrict__ B,
    const float* __restrict__ bias, float* __restrict__ C,
    int ldA, int ldB, int N, int nch, int bkmask) {
    extern __shared__ __align__(128) char smem[];
    const uint32_t sb = smem_u32(smem);
    const int tid = threadIdx.x, lane = tid & 31, wid = tid >> 5;
    const int bm = blockIdx.x * 128, bn = blockIdx.y * 128;
    const int wm = (wid & 1) * 64, wn = (wid >> 1) * 32;

    float acc[4][4][4] = {};

    auto issue = [&](int ch, int buf) {
        int k0 = ch * 64;
        int bk = k0 & bkmask;
        uint32_t abase = sb + buf * HBUF;
        uint32_t bbase = abase + 16384;
#pragma unroll
        for (int i = 0; i < 4; i++) {
            int idx = tid + 256 * i;
            int r = idx >> 3, c = idx & 7;
            uint32_t off = (uint32_t)(r * 128 + ((c ^ (r & 7)) * 16));
            const __half* gp = A + (size_t)(bm + r) * ldA + k0 + c * 8;
            asm volatile("cp.async.cg.shared.global [%0], [%1], 16;"
                         :: "r"(abase + off), "l"(gp));
        }
#pragma unroll
        for (int i = 0; i < 4; i++) {
            int idx = tid + 256 * i;
            int r = idx >> 3, c = idx & 7;
            uint32_t off = (uint32_t)(r * 128 + ((c ^ (r & 7)) * 16));
            const __half* gp = B + (size_t)(bn + r) * ldB + bk + c * 8;
            asm volatile("cp.async.cg.shared.global [%0], [%1], 16;"
                         :: "r"(bbase + off), "l"(gp));
        }
        asm volatile("cp.async.commit_group;" ::: "memory");
    };

    issue(0, 0);

    for (int ch = 0; ch < nch; ch++) {
        int b = ch & 1;
        if (ch + 1 < nch) {
            issue(ch + 1, b ^ 1);
            asm volatile("cp.async.wait_group 1;" ::: "memory");
        } else {
            asm volatile("cp.async.wait_group 0;" ::: "memory");
        }
        __syncthreads();

        uint32_t abase = sb + b * HBUF;
        uint32_t bbase = abase + 16384;
#pragma unroll
        for (int ks = 0; ks < 4; ks++) {
            uint32_t afr[4][4];
#pragma unroll
            for (int mi = 0; mi < 4; mi++) {
                int r = wm + mi * 16 + (lane & 15);
                int cu = ks * 2 + (lane >> 4);
                uint32_t addr = abase + r * 128 + ((cu ^ (r & 7)) * 16);
                ldsm4(afr[mi], addr);
            }
            uint32_t bfr[2][4];
#pragma unroll
            for (int p = 0; p < 2; p++) {
                int r = wn + p * 16 + (lane & 7) + ((lane >> 4) * 8);
                int cu = ks * 2 + ((lane >> 3) & 1);
                uint32_t addr = bbase + r * 128 + ((cu ^ (r & 7)) * 16);
                ldsm4(bfr[p], addr);
            }
#pragma unroll
            for (int mi = 0; mi < 4; mi++)
#pragma unroll
                for (int nj = 0; nj < 4; nj++)
                    mma16816(acc[mi][nj], afr[mi],
                             bfr[nj >> 1][(nj & 1) * 2 + 0],
                             bfr[nj >> 1][(nj & 1) * 2 + 1]);
        }
        __syncthreads();
    }

#pragma unroll
    for (int mi = 0; mi < 4; mi++) {
#pragma unroll
        for (int nj = 0; nj < 4; nj++) {
            int row = bm + wm + mi * 16 + (lane >> 2);
            int col = bn + wn + nj * 8 + (lane & 3) * 2;
            float b0 = bias ? bias[col] : 0.0f;
            float b1 = bias ? bias[col + 1] : 0.0f;
            float2 v0 = make_float2(acc[mi][nj][0] + b0, acc[mi][nj][1] + b1);
            float2 v1 = make_float2(acc[mi][nj][2] + b0, acc[mi][nj][3] + b1);
            *(float2*)(C + (size_t)row * N + col) = v0;
            *(float2*)(C + (size_t)(row + 8) * N + col) = v1;
        }
    }
}

// ---------------------------------------------------------------------------
// Fused HMMA refine MLP.
// CTA = 128 tile rows x one block t. Phase1: H = gelu(X2 @ W1h), K'=128.
// Phase2: delta = H2 @ W2h, K'=512. xb += lam*delta.
// Smem: [0,128K) Hs (phase1: Xs at 0..32K, W1s at 32K..64K), [128K,160K) W2s.
// ---------------------------------------------------------------------------
#define MLPTC_SMEM (131072 + 32768)
__global__ __launch_bounds__(256) void mlp_tc(
    float* __restrict__ xb, const __half* __restrict__ W1p,
    const __half* __restrict__ W2p, const float* __restrict__ lam_logit, int r) {
    extern __shared__ __align__(128) char smem[];
    const uint32_t sb = smem_u32(smem);
    const uint32_t XS = sb, W1S = sb + 32768, HS = sb, W2S = sb + 131072;
    const int tid = threadIdx.x, lane = tid & 31, wid = tid >> 5;
    const int t = blockIdx.y, rt = blockIdx.x;
    const int wm = (wid & 1) * 64;
    float lam = 1.0f;
    if (r > 0) lam = 1.0f / (1.0f + expf(-lam_logit[0]));

    // async-load pre-swizzled weights (linear copies)
    {
        const __half* w1g = W1p + (size_t)t * 16384;
        const __half* w2g = W2p + (size_t)t * 16384;
#pragma unroll
        for (int i = 0; i < 8; i++) {
            int idx = tid + 256 * i;
            asm volatile("cp.async.cg.shared.global [%0], [%1], 16;"
                         :: "r"(W1S + idx * 16), "l"(w1g + idx * 8));
        }
#pragma unroll
        for (int i = 0; i < 8; i++) {
            int idx = tid + 256 * i;
            asm volatile("cp.async.cg.shared.global [%0], [%1], 16;"
                         :: "r"(W2S + idx * 16), "l"(w2g + idx * 8));
        }
        asm volatile("cp.async.commit_group;" ::: "memory");
    }

    // X tile: load fp32, split hi/lo fp16 into Xs (row stride 256B, swizzled)
#pragma unroll
    for (int i = 0; i < 4; i++) {
        int idx = tid + 256 * i;      // 0..1023
        int lr = idx >> 3, c = idx & 7;
        int g = rt * 128 + lr;
        const float* xp = xb + ((size_t)(g >> 2) * 32 + t * 4 + (g & 3)) * 64 + c * 8;
        float4 v0 = *(const float4*)xp;
        float4 v1 = *(const float4*)(xp + 4);
        float vv[8] = {v0.x, v0.y, v0.z, v0.w, v1.x, v1.y, v1.z, v1.w};
        uint4 Hh, Ll;
        uint32_t* hw = (uint32_t*)&Hh;
        uint32_t* lw = (uint32_t*)&Ll;
#pragma unroll
        for (int j = 0; j < 4; j++) {
            float a = vv[2 * j], b = vv[2 * j + 1];
            __half ha = __float2half_rn(a), hb = __float2half_rn(b);
            hw[j] = (uint32_t)__half_as_ushort(ha) |
                    ((uint32_t)__half_as_ushort(hb) << 16);
            lw[j] = pack_h2(a - __half2float(ha), b - __half2float(hb));
        }
        int phh = c ^ (lr & 7);
        *(uint4*)(smem + lr * 256 + phh * 16) = Hh;
        *(uint4*)(smem + lr * 256 + (8 + phh) * 16) = Ll;
    }
    asm volatile("cp.async.wait_group 0;" ::: "memory");
    __syncthreads();

    // Phase 1: acc1[128x256 H tile], warp tile 64x64
    float acc1[4][8][4] = {};
    {
        const int wn1 = (wid >> 1) * 64;
#pragma unroll
        for (int ks = 0; ks < 8; ks++) {
            uint32_t afr[4][4];
#pragma unroll
            for (int mi = 0; mi < 4; mi++) {
                int rr = wm + mi * 16 + (lane & 15);
                int cu = ks * 2 + (lane >> 4);
                int ph = (cu & 8) | ((cu & 7) ^ (rr & 7));
                ldsm4(afr[mi], XS + rr * 256 + ph * 16);
            }
            uint32_t bfr[4][4];
#pragma unroll
            for (int p = 0; p < 4; p++) {
                int rr = wn1 + p * 16 + (lane & 7) + ((lane >> 4) * 8);
                int cu = (ks * 2 + ((lane >> 3) & 1)) & 7;
                int ph = cu ^ (rr & 7);
                ldsm4(bfr[p], W1S + rr * 128 + ph * 16);
            }
#pragma unroll
            for (int mi = 0; mi < 4; mi++)
#pragma unroll
                for (int nj = 0; nj < 8; nj++)
                    mma16816(acc1[mi][nj], afr[mi],
                             bfr[nj >> 1][(nj & 1) * 2 + 0],
                             bfr[nj >> 1][(nj & 1) * 2 + 1]);
        }
        __syncthreads();  // phase1 reads done; Hs may overwrite Xs/W1s

        // gelu + 2-term split into Hs (row stride 1024B, hi chunks 0..31, lo 32..63)
#pragma unroll
        for (int mi = 0; mi < 4; mi++)
#pragma unroll
            for (int nj = 0; nj < 8; nj++) {
                int r0 = wm + mi * 16 + (lane >> 2);
                int n0 = wn1 + nj * 8 + (lane & 3) * 2;
                float g0 = gelu_f(acc1[mi][nj][0]);
                float g1 = gelu_f(acc1[mi][nj][1]);
                float g2 = gelu_f(acc1[mi][nj][2]);
                float g3 = gelu_f(acc1[mi][nj][3]);
                __half h0 = __float2half_rn(g0), h1 = __float2half_rn(g1);
                __half h2 = __float2half_rn(g2), h3 = __float2half_rn(g3);
                uint32_t hi0 = (uint32_t)__half_as_ushort(h0) |
                               ((uint32_t)__half_as_ushort(h1) << 16);
                uint32_t hi1 = (uint32_t)__half_as_ushort(h2) |
                               ((uint32_t)__half_as_ushort(h3) << 16);
                uint32_t lo0 = pack_h2(g0 - __half2float(h0), g1 - __half2float(h1));
                uint32_t lo1 = pack_h2(g2 - __half2float(h2), g3 - __half2float(h3));
                int ch = n0 >> 3, within = (n0 & 7) * 2;
                int ph = (ch & ~7) | ((ch & 7) ^ (r0 & 7));
                char* base0 = smem + r0 * 1024 + within;
                char* base1 = smem + (r0 + 8) * 1024 + within;
                *(uint32_t*)(base0 + ph * 16) = hi0;
                *(uint32_t*)(base0 + (ph + 32) * 16) = lo0;
                *(uint32_t*)(base1 + ph * 16) = hi1;
                *(uint32_t*)(base1 + (ph + 32) * 16) = lo1;
            }
    }
    __syncthreads();

    // Phase 2: delta[128x64], warp tile 64x16, K'=512 (B k wrap 256)
    float acc2[4][2][4] = {};
    const int wn2 = (wid >> 1) * 16;
#pragma unroll
    for (int ks = 0; ks < 32; ks++) {
        uint32_t afr[4][4];
#pragma unroll
        for (int mi = 0; mi < 4; mi++) {
            int rr = wm + mi * 16 + (lane & 15);
            int cu = ks * 2 + (lane >> 4);
            int ph = (cu & ~7) | ((cu & 7) ^ (rr & 7));
            ldsm4(afr[mi], HS + rr * 1024 + ph * 16);
        }
        uint32_t bfr[4];
        {
            int rr = wn2 + (lane & 7) + ((lane >> 4) * 8);
            int cu = (ks * 2 + ((lane >> 3) & 1)) & 31;
            int ph = (cu & ~7) | ((cu & 7) ^ (rr & 7));
            ldsm4(bfr, W2S + rr * 512 + ph * 16);
        }
#pragma unroll
        for (int mi = 0; mi < 4; mi++)
#pragma unroll
            for (int nj = 0; nj < 2; nj++)
                mma16816(acc2[mi][nj], afr[mi], bfr[nj * 2], bfr[nj * 2 + 1]);
    }

    // Epilogue: xb += lam * delta
#pragma unroll
    for (int mi = 0; mi < 4; mi++)
#pragma unroll
        for (int nj = 0; nj < 2; nj++) {
            int r0 = wm + mi * 16 + (lane >> 2);
            int n0 = wn2 + nj * 8 + (lane & 3) * 2;
#pragma unroll
            for (int h = 0; h < 2; h++) {
                int g = rt * 128 + r0 + h * 8;
                float* p = xb + ((size_t)(g >> 2) * 32 + t * 4 + (g & 3)) * 64 + n0;
                float2 old = *(float2*)p;
                old.x += lam * acc2[mi][nj][h * 2 + 0];
                old.y += lam * acc2[mi][nj][h * 2 + 1];
                *(float2*)p = old;
            }
        }
}

// ---------------------------------------------------------------------------
// Embedding gather + pos add
// ---------------------------------------------------------------------------
__global__ void embed_kernel(const int* __restrict__ ids,
                             const float* __restrict__ emb,
                             const float* __restrict__ pos,
                             float* __restrict__ x) {
    int s = blockIdx.x;
    int q = threadIdx.x;
    int id = ids[s];
    float4 e = ((const float4*)(emb + (size_t)id * D_DIM))[q];
    float4 p = ((const float4*)(pos + (size_t)(s & 1023) * D_DIM))[q];
    float4 o;
    o.x = e.x + p.x; o.y = e.y + p.y; o.z = e.z + p.z; o.w = e.w + p.w;
    ((float4*)(x + (size_t)s * D_DIM))[q] = o;
}

// ---------------------------------------------------------------------------
// Z pass
// ---------------------------------------------------------------------------
__global__ void zpass_kernel(const float* __restrict__ xb,
                             const float* __restrict__ Wz,
                             float* __restrict__ zhat,
                             float* __restrict__ pcm, int r) {
    __shared__ float zs[64];
    __shared__ float red[64];
    const int st = blockIdx.x;
    const int t = st & 7;
    const int d = threadIdx.x;
    const float* xp = xb + (size_t)st * 256;
    float z = 0.25f * (xp[d] + xp[64 + d] + xp[128 + d] + xp[192 + d]);
    zs[d] = z;
    float sq = 0.0f;
    if (r > 0) {
        float diff = zhat[(size_t)st * 64 + d] - z;
        sq = diff * diff;
    }
    __syncthreads();
    const float* wz = Wz + t * 4096;
    float acc = 0.0f;
#pragma unroll
    for (int k = 0; k < 64; k++) acc = fmaf(zs[k], wz[k * 64 + d], acc);
    red[d] = sq;
    __syncthreads();
    for (int o = 32; o > 0; o >>= 1) {
        if (d < o) red[d] += red[d + o];
        __syncthreads();
    }
    if (r > 0 && d == 0) pcm[(size_t)(r - 1) * (S_TOT * NB) + st] = red[0];
    zhat[(size_t)st * 64 + d] = acc;
}

// ---------------------------------------------------------------------------
// LayerNorm (in place)
// ---------------------------------------------------------------------------
__global__ void ln_kernel(float* __restrict__ x, const float* __restrict__ g,
                          const float* __restrict__ b) {
    __shared__ float red[256];
    const int s = blockIdx.x, tid = threadIdx.x;
    float4* row = (float4*)(x + (size_t)s * D_DIM);
    float4 v = row[tid];
    red[tid] = v.x + v.y + v.z + v.w;
    __syncthreads();
    for (int o = 128; o > 0; o >>= 1) {
        if (tid < o) red[tid] += red[tid + o];
        __syncthreads();
    }
    float mu = red[0] * (1.0f / 1024.0f);
    __syncthreads();
    float dx = v.x - mu, dy = v.y - mu, dz = v.z - mu, dw = v.w - mu;
    red[tid] = dx * dx + dy * dy + dz * dz + dw * dw;
    __syncthreads();
    for (int o = 128; o > 0; o >>= 1) {
        if (tid < o) red[tid] += red[tid + o];
        __syncthreads();
    }
    float rstd = rsqrtf(red[0] * (1.0f / 1024.0f) + 1e-5f);
    float4 gg = ((const float4*)g)[tid];
    float4 bb = ((const float4*)b)[tid];
    float4 o4;
    o4.x = dx * rstd * gg.x + bb.x;
    o4.y = dy * rstd * gg.y + bb.y;
    o4.z = dz * rstd * gg.z + bb.z;
    o4.w = dw * rstd * gg.w + bb.w;
    row[tid] = o4;
}

// ---------------------------------------------------------------------------
// Deterministic aux reduction
// ---------------------------------------------------------------------------
__global__ void aux_kernel(const float* __restrict__ pcm, float* __restrict__ out) {
    __shared__ float red[256];
    const int tid = threadIdx.x;
    float s = 0.0f;
    for (int i = tid; i < 2 * S_TOT * NB; i += 256) s += pcm[i];
    red[tid] = s;
    __syncthreads();
    for (int o = 128; o > 0; o >>= 1) {
        if (tid < o) red[tid] += red[tid + o];
        __syncthreads();
    }
    if (tid == 0) out[0] = 0.1f * red[0] / 262144.0f;
}

// ---------------------------------------------------------------------------
extern "C" void kernel_launch(void* const* d_in, const int* in_sizes, int n_in,
                              void* d_out, int out_size) {
    const int*   ids  = (const int*)d_in[0];
    const float* emb  = (const float*)d_in[1];
    const float* pos  = (const float*)d_in[2];
    const float* fo_w = (const float*)d_in[3];
    const float* fo_b = (const float*)d_in[4];
    const float* W1   = (const float*)d_in[5];
    const float* W2   = (const float*)d_in[6];
    const float* Wz   = (const float*)d_in[7];
    const float* fi_w = (const float*)d_in[8];
    const float* fi_b = (const float*)d_in[9];
    const float* ln_g = (const float*)d_in[10];
    const float* ln_b = (const float*)d_in[11];
    const float* lamp = (const float*)d_in[12];
    float* out = (float*)d_out;

    float *x, *xb, *zhat, *pcm;
    __half *Ah, *Bh, *Axo, *Bfo, *Axi, *Bfi, *W1p, *W2p;
    cudaGetSymbolAddress((void**)&x,    g_x);
    cudaGetSymbolAddress((void**)&xb,   g_xb);
    cudaGetSymbolAddress((void**)&zhat, g_zhat);
    cudaGetSymbolAddress((void**)&pcm,  g_pcm);
    cudaGetSymbolAddress((void**)&Ah,   g_Ah);
    cudaGetSymbolAddress((void**)&Bh,   g_Bh);
    cudaGetSymbolAddress((void**)&Axo,  g_Axo);
    cudaGetSymbolAddress((void**)&Bfo,  g_Bfo);
    cudaGetSymbolAddress((void**)&Axi,  g_Axi);
    cudaGetSymbolAddress((void**)&Bfi,  g_Bfi);
    cudaGetSymbolAddress((void**)&W1p,  g_W1p);
    cudaGetSymbolAddress((void**)&W2p,  g_W2p);

    cudaFuncSetAttribute(gemm_hmma, cudaFuncAttributeMaxDynamicSharedMemorySize,
                         HSMEM);
    cudaFuncSetAttribute(mlp_tc, cudaFuncAttributeMaxDynamicSharedMemorySize,
                         MLPTC_SMEM);

    // 1. embed + weight conversions
    embed_kernel<<<S_TOT, 256>>>(ids, emb, pos, x);
    convB_h<<<V_DIM, 256>>>(emb, Bh);
    convB3T<<<dim3(D_DIM / 32, T_DIM / 32), 256>>>(fo_w, Bfo, D_DIM, T_DIM);
    convB3T<<<dim3(T_DIM / 32, D_DIM / 32), 256>>>(fi_w, Bfi, T_DIM, D_DIM);
    convW1p<<<512, 256>>>(W1, W1p);
    convW2p<<<512, 256>>>(W2, W2p);

    // 2. fan_out (HMMA 3-term)
    convA3<<<S_TOT, 256>>>(x, Axo, D_DIM);
    gemm_hmma<<<dim3(S_TOT / 128, T_DIM / 128), 256, HSMEM>>>(
        Axo, Bfo, fo_b, xb, 3 * D_DIM, 3 * D_DIM, T_DIM, 3 * D_DIM / 64, ~0);

    // 3. refine passes (zpass fp32, mlp on tensor cores)
    for (int r = 0; r < 3; r++) {
        zpass_kernel<<<S_TOT * NB, 64>>>(xb, Wz, zhat, pcm, r);
        mlp_tc<<<dim3(128, NB), 256, MLPTC_SMEM>>>(xb, W1p, W2p, lamp, r);
    }

    // 4. fan_in (HMMA 3-term)
    convA3<<<S_TOT, 256>>>(xb, Axi, T_DIM);
    gemm_hmma<<<dim3(S_TOT / 128, D_DIM / 128), 256, HSMEM>>>(
        Axi, Bfi, fi_b, x, 3 * T_DIM, 3 * T_DIM, D_DIM, 3 * T_DIM / 64, ~0);

    // 5. layernorm
    ln_kernel<<<S_TOT, 256>>>(x, ln_g, ln_b);

    // 6. logits (HMMA 2-term A-split, B k-wrap)
    convA_h<<<S_TOT, 256>>>(x, Ah);
    gemm_hmma<<<dim3(S_TOT / 128, V_DIM / 128), 256, HSMEM>>>(
        Ah, Bh, (const float*)0, out, 2048, 1024, V_DIM, 32, 1023);

    // 7. aux loss
    if (out_size > S_TOT * V_DIM) {
        aux_kernel<<<1, 256>>>(pcm, out + (size_t)S_TOT * V_DIM);
    }
}